// round 10
// baseline (speedup 1.0000x reference)
#include <cuda_runtime.h>

#define PI_F 3.14159265358979323846f

static __device__ __forceinline__ float f_rsqrt(float x){ float r; asm("rsqrt.approx.f32 %0, %1;" : "=f"(r) : "f"(x)); return r; }
static __device__ __forceinline__ float f_sqrt (float x){ float r; asm("sqrt.approx.f32 %0, %1;"  : "=f"(r) : "f"(x)); return r; }
static __device__ __forceinline__ float f_rcp  (float x){ float r; asm("rcp.approx.f32 %0, %1;"   : "=f"(r) : "f"(x)); return r; }
static __device__ __forceinline__ float f_tanh (float x){ float r; asm("tanh.approx.f32 %0, %1;"  : "=f"(r) : "f"(x)); return r; }

struct c32 { float x, y; };
static __device__ __forceinline__ c32 cmul(c32 a, c32 b){
    c32 r;
    r.x = fmaf(a.x, b.x, -a.y * b.y);
    r.y = fmaf(a.x, b.y,  a.y * b.x);
    return r;
}

static __device__ __forceinline__ constexpr int cnotp(int j, int c, int tq){
    return j ^ (((j >> (3 - c)) & 1) << (3 - tq));
}

constexpr int THREADS = 256;
constexpr int BATCH   = 65536;
constexpr int BLOCKS  = BATCH / 32;    // 2048 one-shot blocks, 32 rows each

// ---------------------------------------------------------------------------
// full 4-qubit circuit for one row (per-lane registers)
// ---------------------------------------------------------------------------
static __device__ __forceinline__ float4 circuit(float f0, float f1, float f2, float f3,
                                                 const float2 (*rotm)[4])
{
    auto mkv = [](float fq, c32& v0, c32& v1) {
        float u  = f_sqrt(fmaf(fq, fq, 1.f));
        float ta = fq * f_rcp(1.f + u);
        float c1 = f_rsqrt(fmaf(ta, ta, 1.f));
        float s1 = ta * c1;
        float g  = fq * fq;
        float u2 = f_sqrt(fmaf(g, g, 1.f));
        float tb = g * f_rcp(1.f + u2);
        float cb = f_rsqrt(fmaf(tb, tb, 1.f));
        float sb = tb * cb;
        const float r2 = 0.7071067811865476f;
        float p = (c1 - s1) * r2;
        float q = (c1 + s1) * r2;
        v0.x = p * cb; v0.y = -p * sb;
        v1.x = q * cb; v1.y =  q * sb;
    };
    c32 va0, va1, vb0, vb1, vc0, vc1, vd0, vd1;
    mkv(f0, va0, va1); mkv(f1, vb0, vb1); mkv(f2, vc0, vc1); mkv(f3, vd0, vd1);

    c32 w01[4] = { cmul(va0, vb0), cmul(va0, vb1), cmul(va1, vb0), cmul(va1, vb1) };
    c32 w23[4] = { cmul(vc0, vd0), cmul(vc0, vd1), cmul(vc1, vd0), cmul(vc1, vd1) };
    c32 psi[16];
    #pragma unroll
    for (int j = 0; j < 16; j++) psi[j] = cmul(w01[j >> 2], w23[j & 3]);

    // CNOT ring (compile-time index permutations)
    {
        c32 tmp[16];
        #pragma unroll
        for (int j = 0; j < 16; j++) tmp[j] = psi[cnotp(j, 0, 1)];
        #pragma unroll
        for (int j = 0; j < 16; j++) psi[j] = tmp[j];
        #pragma unroll
        for (int j = 0; j < 16; j++) tmp[j] = psi[cnotp(j, 1, 2)];
        #pragma unroll
        for (int j = 0; j < 16; j++) psi[j] = tmp[j];
        #pragma unroll
        for (int j = 0; j < 16; j++) tmp[j] = psi[cnotp(j, 2, 3)];
        #pragma unroll
        for (int j = 0; j < 16; j++) psi[j] = tmp[j];
        #pragma unroll
        for (int j = 0; j < 16; j++) tmp[j] = psi[cnotp(j, 3, 0)];
        #pragma unroll
        for (int j = 0; j < 16; j++) psi[j] = tmp[j];
    }

    // Rot gates (constant matrices broadcast from smem)
    #pragma unroll
    for (int q = 0; q < 4; q++) {
        float2 m00 = rotm[q][0], m01 = rotm[q][1], m10 = rotm[q][2], m11 = rotm[q][3];
        c32 U00 = {m00.x, m00.y}, U01 = {m01.x, m01.y};
        c32 U10 = {m10.x, m10.y}, U11 = {m11.x, m11.y};
        const int mask = 8 >> q;
        #pragma unroll
        for (int j = 0; j < 16; j++) {
            if ((j & mask) == 0) {
                const int j1 = j | mask;
                c32 a = psi[j], b = psi[j1];
                c32 t0 = cmul(U00, a), t1 = cmul(U01, b);
                c32 t2 = cmul(U10, a), t3 = cmul(U11, b);
                psi[j].x  = t0.x + t1.x; psi[j].y  = t0.y + t1.y;
                psi[j1].x = t2.x + t3.x; psi[j1].y = t2.y + t3.y;
            }
        }
    }

    float z0 = 0.f, z1 = 0.f, z2 = 0.f, z3 = 0.f;
    #pragma unroll
    for (int j = 0; j < 16; j++) {
        float p = fmaf(psi[j].x, psi[j].x, psi[j].y * psi[j].y);
        z0 += (j & 8) ? -p : p;
        z1 += (j & 4) ? -p : p;
        z2 += (j & 2) ? -p : p;
        z3 += (j & 1) ? -p : p;
    }
    return make_float4(z0, z1, z2, z3);
}

__global__ __launch_bounds__(THREADS, 3)
void qp_fused(const float* __restrict__ x,
              const float* __restrict__ pre_w,
              const float* __restrict__ pre_b,
              const float* __restrict__ qw,
              const float* __restrict__ post_w,
              const float* __restrict__ post_b,
              float4* __restrict__ out4)
{
    __shared__ __align__(16) float wsm[4 * 1024];   // pre_w as stored: [q][1024]
    __shared__ float2 rotm[4][4];
    __shared__ float  pbq[4];
    __shared__ float4 zsm[32];

    const int t = threadIdx.x;
    {
        const float4* src = (const float4*)pre_w;
        float4*       dst = (float4*)wsm;
        #pragma unroll
        for (int i = 0; i < 4; i++) dst[t + THREADS * i] = src[t + THREADS * i];
    }
    if (t < 4) {
        pbq[t] = pre_b[t];
        float phi = qw[t * 3 + 0], th = qw[t * 3 + 1], om = qw[t * 3 + 2];
        float st, ct; sincosf(0.5f * th,         &st, &ct);
        float sp, cp; sincosf(0.5f * (phi + om), &sp, &cp);
        float sm, cm; sincosf(0.5f * (phi - om), &sm, &cm);
        rotm[t][0] = make_float2( ct * cp, -ct * sp);
        rotm[t][1] = make_float2(-st * cm, -st * sm);
        rotm[t][2] = make_float2( st * cm, -st * sm);
        rotm[t][3] = make_float2( ct * cp,  ct * sp);
    }
    __syncthreads();

    const int warp = t >> 5, lane = t & 31;
    const int row0 = blockIdx.x * 32;

    // ---------------- Phase A: h = x @ pre_w.T, 4 rows per warp -----------
    {
        const int rloc = lane >> 3;                // 0..3
        const int cgrp = lane & 7;                 // 0..7
        const int row  = row0 + warp * 4 + rloc;
        const float4* __restrict__ xr = (const float4*)x + (size_t)row * 256 + cgrp;
        const float4* __restrict__ w4a = (const float4*)(wsm);
        const float4* __restrict__ w4b = (const float4*)(wsm + 1024);
        const float4* __restrict__ w4c = (const float4*)(wsm + 2048);
        const float4* __restrict__ w4d = (const float4*)(wsm + 3072);

        float a0 = 0.f, a1 = 0.f, a2 = 0.f, a3 = 0.f;
        #pragma unroll 16
        for (int i = 0; i < 32; i++) {
            const int col = cgrp + 8 * i;
            float4 xv = __ldcs(xr + 8 * i);
            float4 w0 = w4a[col], w1 = w4b[col], w2 = w4c[col], w3 = w4d[col];
            a0 = fmaf(xv.x, w0.x, fmaf(xv.y, w0.y, fmaf(xv.z, w0.z, fmaf(xv.w, w0.w, a0))));
            a1 = fmaf(xv.x, w1.x, fmaf(xv.y, w1.y, fmaf(xv.z, w1.z, fmaf(xv.w, w1.w, a1))));
            a2 = fmaf(xv.x, w2.x, fmaf(xv.y, w2.y, fmaf(xv.z, w2.z, fmaf(xv.w, w2.w, a2))));
            a3 = fmaf(xv.x, w3.x, fmaf(xv.y, w3.y, fmaf(xv.z, w3.z, fmaf(xv.w, w3.w, a3))));
        }
        // reduce across the 8 lanes of each row group
        #pragma unroll
        for (int off = 1; off < 8; off <<= 1) {
            a0 += __shfl_xor_sync(0xffffffffu, a0, off);
            a1 += __shfl_xor_sync(0xffffffffu, a1, off);
            a2 += __shfl_xor_sync(0xffffffffu, a2, off);
            a3 += __shfl_xor_sync(0xffffffffu, a3, off);
        }

        const float f0 = f_tanh(a0 + pbq[0]) * PI_F;
        const float f1 = f_tanh(a1 + pbq[1]) * PI_F;
        const float f2 = f_tanh(a2 + pbq[2]) * PI_F;
        const float f3 = f_tanh(a3 + pbq[3]) * PI_F;

        float4 z = circuit(f0, f1, f2, f3, rotm);
        if (cgrp == 0) zsm[warp * 4 + rloc] = z;
    }
    __syncthreads();

    // ---------------- Phase B: out = z @ post_w.T + post_b ----------------
    // thread t owns out columns 4t..4t+3; weights held in registers, reused
    // across all 32 rows.  Fully unrolled so ptxas can batch the STG stream.
    {
        const float4* pwv = (const float4*)post_w;
        float4 pw0 = pwv[4 * t + 0];
        float4 pw1 = pwv[4 * t + 1];
        float4 pw2 = pwv[4 * t + 2];
        float4 pw3 = pwv[4 * t + 3];
        float4 bv  = ((const float4*)post_b)[t];

        float4* orow = out4 + (size_t)row0 * 256 + t;
        #pragma unroll
        for (int r = 0; r < 32; r++) {
            float4 zv = zsm[r];
            float4 o;
            o.x = fmaf(zv.x, pw0.x, fmaf(zv.y, pw0.y, fmaf(zv.z, pw0.z, fmaf(zv.w, pw0.w, bv.x))));
            o.y = fmaf(zv.x, pw1.x, fmaf(zv.y, pw1.y, fmaf(zv.z, pw1.z, fmaf(zv.w, pw1.w, bv.y))));
            o.z = fmaf(zv.x, pw2.x, fmaf(zv.y, pw2.y, fmaf(zv.z, pw2.z, fmaf(zv.w, pw2.w, bv.z))));
            o.w = fmaf(zv.x, pw3.x, fmaf(zv.y, pw3.y, fmaf(zv.z, pw3.z, fmaf(zv.w, pw3.w, bv.w))));
            __stcs(orow + (size_t)r * 256, o);
        }
    }
}

extern "C" void kernel_launch(void* const* d_in, const int* in_sizes, int n_in,
                              void* d_out, int out_size)
{
    const float* x      = (const float*)d_in[0];
    const float* pre_w  = (const float*)d_in[1];
    const float* pre_b  = (const float*)d_in[2];
    const float* qw     = (const float*)d_in[3];
    const float* post_w = (const float*)d_in[4];
    const float* post_b = (const float*)d_in[5];
    (void)in_sizes; (void)n_in; (void)out_size;

    qp_fused<<<BLOCKS, THREADS>>>(x, pre_w, pre_b, qw, post_w, post_b, (float4*)d_out);
}

// round 11
// speedup vs baseline: 1.0224x; 1.0224x over previous
#include <cuda_runtime.h>

#define PI_F 3.14159265358979323846f

static __device__ __forceinline__ float f_rsqrt(float x){ float r; asm("rsqrt.approx.f32 %0, %1;" : "=f"(r) : "f"(x)); return r; }
static __device__ __forceinline__ float f_sqrt (float x){ float r; asm("sqrt.approx.f32 %0, %1;"  : "=f"(r) : "f"(x)); return r; }
static __device__ __forceinline__ float f_rcp  (float x){ float r; asm("rcp.approx.f32 %0, %1;"   : "=f"(r) : "f"(x)); return r; }
static __device__ __forceinline__ float f_tanh (float x){ float r; asm("tanh.approx.f32 %0, %1;"  : "=f"(r) : "f"(x)); return r; }

struct c32 { float x, y; };
static __device__ __forceinline__ c32 cmul(c32 a, c32 b){
    c32 r;
    r.x = fmaf(a.x, b.x, -a.y * b.y);
    r.y = fmaf(a.x, b.y,  a.y * b.x);
    return r;
}

static __device__ __forceinline__ constexpr int cnotp(int j, int c, int tq){
    return j ^ (((j >> (3 - c)) & 1) << (3 - tq));
}

constexpr int THREADS  = 128;
constexpr int ROWS_BLK = 16;
constexpr int BATCH    = 65536;
constexpr int BLOCKS   = BATCH / ROWS_BLK;   // 4096 one-shot blocks, 16 rows each

// ---------------------------------------------------------------------------
// full 4-qubit circuit for one row (per-lane registers)
// ---------------------------------------------------------------------------
static __device__ __forceinline__ float4 circuit(float f0, float f1, float f2, float f3,
                                                 const float2 (*rotm)[4])
{
    auto mkv = [](float fq, c32& v0, c32& v1) {
        float u  = f_sqrt(fmaf(fq, fq, 1.f));
        float ta = fq * f_rcp(1.f + u);
        float c1 = f_rsqrt(fmaf(ta, ta, 1.f));
        float s1 = ta * c1;
        float g  = fq * fq;
        float u2 = f_sqrt(fmaf(g, g, 1.f));
        float tb = g * f_rcp(1.f + u2);
        float cb = f_rsqrt(fmaf(tb, tb, 1.f));
        float sb = tb * cb;
        const float r2 = 0.7071067811865476f;
        float p = (c1 - s1) * r2;
        float q = (c1 + s1) * r2;
        v0.x = p * cb; v0.y = -p * sb;
        v1.x = q * cb; v1.y =  q * sb;
    };
    c32 va0, va1, vb0, vb1, vc0, vc1, vd0, vd1;
    mkv(f0, va0, va1); mkv(f1, vb0, vb1); mkv(f2, vc0, vc1); mkv(f3, vd0, vd1);

    c32 w01[4] = { cmul(va0, vb0), cmul(va0, vb1), cmul(va1, vb0), cmul(va1, vb1) };
    c32 w23[4] = { cmul(vc0, vd0), cmul(vc0, vd1), cmul(vc1, vd0), cmul(vc1, vd1) };
    c32 psi[16];
    #pragma unroll
    for (int j = 0; j < 16; j++) psi[j] = cmul(w01[j >> 2], w23[j & 3]);

    // CNOT ring (compile-time index permutations)
    {
        c32 tmp[16];
        #pragma unroll
        for (int j = 0; j < 16; j++) tmp[j] = psi[cnotp(j, 0, 1)];
        #pragma unroll
        for (int j = 0; j < 16; j++) psi[j] = tmp[j];
        #pragma unroll
        for (int j = 0; j < 16; j++) tmp[j] = psi[cnotp(j, 1, 2)];
        #pragma unroll
        for (int j = 0; j < 16; j++) psi[j] = tmp[j];
        #pragma unroll
        for (int j = 0; j < 16; j++) tmp[j] = psi[cnotp(j, 2, 3)];
        #pragma unroll
        for (int j = 0; j < 16; j++) psi[j] = tmp[j];
        #pragma unroll
        for (int j = 0; j < 16; j++) tmp[j] = psi[cnotp(j, 3, 0)];
        #pragma unroll
        for (int j = 0; j < 16; j++) psi[j] = tmp[j];
    }

    // Rot gates (constant matrices broadcast from smem)
    #pragma unroll
    for (int q = 0; q < 4; q++) {
        float2 m00 = rotm[q][0], m01 = rotm[q][1], m10 = rotm[q][2], m11 = rotm[q][3];
        c32 U00 = {m00.x, m00.y}, U01 = {m01.x, m01.y};
        c32 U10 = {m10.x, m10.y}, U11 = {m11.x, m11.y};
        const int mask = 8 >> q;
        #pragma unroll
        for (int j = 0; j < 16; j++) {
            if ((j & mask) == 0) {
                const int j1 = j | mask;
                c32 a = psi[j], b = psi[j1];
                c32 t0 = cmul(U00, a), t1 = cmul(U01, b);
                c32 t2 = cmul(U10, a), t3 = cmul(U11, b);
                psi[j].x  = t0.x + t1.x; psi[j].y  = t0.y + t1.y;
                psi[j1].x = t2.x + t3.x; psi[j1].y = t2.y + t3.y;
            }
        }
    }

    float z0 = 0.f, z1 = 0.f, z2 = 0.f, z3 = 0.f;
    #pragma unroll
    for (int j = 0; j < 16; j++) {
        float p = fmaf(psi[j].x, psi[j].x, psi[j].y * psi[j].y);
        z0 += (j & 8) ? -p : p;
        z1 += (j & 4) ? -p : p;
        z2 += (j & 2) ? -p : p;
        z3 += (j & 1) ? -p : p;
    }
    return make_float4(z0, z1, z2, z3);
}

__global__ __launch_bounds__(THREADS, 6)
void qp_fused(const float* __restrict__ x,
              const float* __restrict__ pre_w,
              const float* __restrict__ pre_b,
              const float* __restrict__ qw,
              const float* __restrict__ post_w,
              const float* __restrict__ post_b,
              float4* __restrict__ out4)
{
    __shared__ __align__(16) float wsm[4 * 1024];   // pre_w as stored: [q][1024]
    __shared__ float2 rotm[4][4];
    __shared__ float  pbq[4];
    __shared__ float4 zsm[ROWS_BLK];

    const int t = threadIdx.x;
    {
        const float4* src = (const float4*)pre_w;
        float4*       dst = (float4*)wsm;
        #pragma unroll
        for (int i = 0; i < 8; i++) dst[t + THREADS * i] = src[t + THREADS * i];
    }
    if (t < 4) {
        pbq[t] = pre_b[t];
        float phi = qw[t * 3 + 0], th = qw[t * 3 + 1], om = qw[t * 3 + 2];
        float st, ct; sincosf(0.5f * th,         &st, &ct);
        float sp, cp; sincosf(0.5f * (phi + om), &sp, &cp);
        float sm, cm; sincosf(0.5f * (phi - om), &sm, &cm);
        rotm[t][0] = make_float2( ct * cp, -ct * sp);
        rotm[t][1] = make_float2(-st * cm, -st * sm);
        rotm[t][2] = make_float2( st * cm, -st * sm);
        rotm[t][3] = make_float2( ct * cp,  ct * sp);
    }
    __syncthreads();

    const int warp = t >> 5, lane = t & 31;
    const int row0 = blockIdx.x * ROWS_BLK;

    // ---------------- Phase A: h = x @ pre_w.T, 4 rows per warp -----------
    {
        const int rloc = lane >> 3;                // 0..3
        const int cgrp = lane & 7;                 // 0..7
        const int row  = row0 + warp * 4 + rloc;
        const float4* __restrict__ xr = (const float4*)x + (size_t)row * 256 + cgrp;
        const float4* __restrict__ w4a = (const float4*)(wsm);
        const float4* __restrict__ w4b = (const float4*)(wsm + 1024);
        const float4* __restrict__ w4c = (const float4*)(wsm + 2048);
        const float4* __restrict__ w4d = (const float4*)(wsm + 3072);

        float a0 = 0.f, a1 = 0.f, a2 = 0.f, a3 = 0.f;
        #pragma unroll 8
        for (int i = 0; i < 32; i++) {
            const int col = cgrp + 8 * i;
            float4 xv = __ldcs(xr + 8 * i);
            float4 w0 = w4a[col], w1 = w4b[col], w2 = w4c[col], w3 = w4d[col];
            a0 = fmaf(xv.x, w0.x, fmaf(xv.y, w0.y, fmaf(xv.z, w0.z, fmaf(xv.w, w0.w, a0))));
            a1 = fmaf(xv.x, w1.x, fmaf(xv.y, w1.y, fmaf(xv.z, w1.z, fmaf(xv.w, w1.w, a1))));
            a2 = fmaf(xv.x, w2.x, fmaf(xv.y, w2.y, fmaf(xv.z, w2.z, fmaf(xv.w, w2.w, a2))));
            a3 = fmaf(xv.x, w3.x, fmaf(xv.y, w3.y, fmaf(xv.z, w3.z, fmaf(xv.w, w3.w, a3))));
        }
        // reduce across the 8 lanes of each row group
        #pragma unroll
        for (int off = 1; off < 8; off <<= 1) {
            a0 += __shfl_xor_sync(0xffffffffu, a0, off);
            a1 += __shfl_xor_sync(0xffffffffu, a1, off);
            a2 += __shfl_xor_sync(0xffffffffu, a2, off);
            a3 += __shfl_xor_sync(0xffffffffu, a3, off);
        }

        const float f0 = f_tanh(a0 + pbq[0]) * PI_F;
        const float f1 = f_tanh(a1 + pbq[1]) * PI_F;
        const float f2 = f_tanh(a2 + pbq[2]) * PI_F;
        const float f3 = f_tanh(a3 + pbq[3]) * PI_F;

        float4 z = circuit(f0, f1, f2, f3, rotm);
        if (cgrp == 0) zsm[warp * 4 + rloc] = z;
    }
    __syncthreads();

    // ---------------- Phase B: out = z @ post_w.T + post_b ----------------
    // thread t owns float4-columns t and t+128; weights held in registers,
    // reused across all 16 rows.
    {
        const float4* pwv = (const float4*)post_w;
        #pragma unroll
        for (int h = 0; h < 2; h++) {
            const int c = t + 128 * h;
            float4 pw0 = pwv[4 * c + 0];
            float4 pw1 = pwv[4 * c + 1];
            float4 pw2 = pwv[4 * c + 2];
            float4 pw3 = pwv[4 * c + 3];
            float4 bv  = ((const float4*)post_b)[c];

            float4* ocol = out4 + (size_t)row0 * 256 + c;
            #pragma unroll 8
            for (int r = 0; r < ROWS_BLK; r++) {
                float4 zv = zsm[r];
                float4 o;
                o.x = fmaf(zv.x, pw0.x, fmaf(zv.y, pw0.y, fmaf(zv.z, pw0.z, fmaf(zv.w, pw0.w, bv.x))));
                o.y = fmaf(zv.x, pw1.x, fmaf(zv.y, pw1.y, fmaf(zv.z, pw1.z, fmaf(zv.w, pw1.w, bv.y))));
                o.z = fmaf(zv.x, pw2.x, fmaf(zv.y, pw2.y, fmaf(zv.z, pw2.z, fmaf(zv.w, pw2.w, bv.z))));
                o.w = fmaf(zv.x, pw3.x, fmaf(zv.y, pw3.y, fmaf(zv.z, pw3.z, fmaf(zv.w, pw3.w, bv.w))));
                __stcs(ocol + (size_t)r * 256, o);
            }
        }
    }
}

extern "C" void kernel_launch(void* const* d_in, const int* in_sizes, int n_in,
                              void* d_out, int out_size)
{
    const float* x      = (const float*)d_in[0];
    const float* pre_w  = (const float*)d_in[1];
    const float* pre_b  = (const float*)d_in[2];
    const float* qw     = (const float*)d_in[3];
    const float* post_w = (const float*)d_in[4];
    const float* post_b = (const float*)d_in[5];
    (void)in_sizes; (void)n_in; (void)out_size;

    qp_fused<<<BLOCKS, THREADS>>>(x, pre_w, pre_b, qw, post_w, post_b, (float4*)d_out);
}

// round 12
// speedup vs baseline: 1.0404x; 1.0177x over previous
#include <cuda_runtime.h>

#define PI_F 3.14159265358979323846f

static __device__ __forceinline__ float f_rsqrt(float x){ float r; asm("rsqrt.approx.f32 %0, %1;" : "=f"(r) : "f"(x)); return r; }
static __device__ __forceinline__ float f_sqrt (float x){ float r; asm("sqrt.approx.f32 %0, %1;"  : "=f"(r) : "f"(x)); return r; }
static __device__ __forceinline__ float f_rcp  (float x){ float r; asm("rcp.approx.f32 %0, %1;"   : "=f"(r) : "f"(x)); return r; }
static __device__ __forceinline__ float f_tanh (float x){ float r; asm("tanh.approx.f32 %0, %1;"  : "=f"(r) : "f"(x)); return r; }

// streaming load with 256B L2 prefetch: stages the successor 128B line into L2
static __device__ __forceinline__ float4 ldcs256(const float4* p){
    float4 v;
    asm("ld.global.cs.L2::256B.v4.f32 {%0,%1,%2,%3}, [%4];"
        : "=f"(v.x), "=f"(v.y), "=f"(v.z), "=f"(v.w) : "l"(p));
    return v;
}

struct c32 { float x, y; };
static __device__ __forceinline__ c32 cmul(c32 a, c32 b){
    c32 r;
    r.x = fmaf(a.x, b.x, -a.y * b.y);
    r.y = fmaf(a.x, b.y,  a.y * b.x);
    return r;
}

static __device__ __forceinline__ constexpr int cnotp(int j, int c, int tq){
    return j ^ (((j >> (3 - c)) & 1) << (3 - tq));
}

constexpr int THREADS  = 128;
constexpr int ROWS_BLK = 16;
constexpr int BATCH    = 65536;
constexpr int BLOCKS   = BATCH / ROWS_BLK;   // 4096 one-shot blocks, 16 rows each

// ---------------------------------------------------------------------------
// full 4-qubit circuit for one row (per-lane registers)
// ---------------------------------------------------------------------------
static __device__ __forceinline__ float4 circuit(float f0, float f1, float f2, float f3,
                                                 const float2 (*rotm)[4])
{
    auto mkv = [](float fq, c32& v0, c32& v1) {
        float u  = f_sqrt(fmaf(fq, fq, 1.f));
        float ta = fq * f_rcp(1.f + u);
        float c1 = f_rsqrt(fmaf(ta, ta, 1.f));
        float s1 = ta * c1;
        float g  = fq * fq;
        float u2 = f_sqrt(fmaf(g, g, 1.f));
        float tb = g * f_rcp(1.f + u2);
        float cb = f_rsqrt(fmaf(tb, tb, 1.f));
        float sb = tb * cb;
        const float r2 = 0.7071067811865476f;
        float p = (c1 - s1) * r2;
        float q = (c1 + s1) * r2;
        v0.x = p * cb; v0.y = -p * sb;
        v1.x = q * cb; v1.y =  q * sb;
    };
    c32 va0, va1, vb0, vb1, vc0, vc1, vd0, vd1;
    mkv(f0, va0, va1); mkv(f1, vb0, vb1); mkv(f2, vc0, vc1); mkv(f3, vd0, vd1);

    c32 w01[4] = { cmul(va0, vb0), cmul(va0, vb1), cmul(va1, vb0), cmul(va1, vb1) };
    c32 w23[4] = { cmul(vc0, vd0), cmul(vc0, vd1), cmul(vc1, vd0), cmul(vc1, vd1) };
    c32 psi[16];
    #pragma unroll
    for (int j = 0; j < 16; j++) psi[j] = cmul(w01[j >> 2], w23[j & 3]);

    // CNOT ring (compile-time index permutations)
    {
        c32 tmp[16];
        #pragma unroll
        for (int j = 0; j < 16; j++) tmp[j] = psi[cnotp(j, 0, 1)];
        #pragma unroll
        for (int j = 0; j < 16; j++) psi[j] = tmp[j];
        #pragma unroll
        for (int j = 0; j < 16; j++) tmp[j] = psi[cnotp(j, 1, 2)];
        #pragma unroll
        for (int j = 0; j < 16; j++) psi[j] = tmp[j];
        #pragma unroll
        for (int j = 0; j < 16; j++) tmp[j] = psi[cnotp(j, 2, 3)];
        #pragma unroll
        for (int j = 0; j < 16; j++) psi[j] = tmp[j];
        #pragma unroll
        for (int j = 0; j < 16; j++) tmp[j] = psi[cnotp(j, 3, 0)];
        #pragma unroll
        for (int j = 0; j < 16; j++) psi[j] = tmp[j];
    }

    // Rot gates (constant matrices broadcast from smem)
    #pragma unroll
    for (int q = 0; q < 4; q++) {
        float2 m00 = rotm[q][0], m01 = rotm[q][1], m10 = rotm[q][2], m11 = rotm[q][3];
        c32 U00 = {m00.x, m00.y}, U01 = {m01.x, m01.y};
        c32 U10 = {m10.x, m10.y}, U11 = {m11.x, m11.y};
        const int mask = 8 >> q;
        #pragma unroll
        for (int j = 0; j < 16; j++) {
            if ((j & mask) == 0) {
                const int j1 = j | mask;
                c32 a = psi[j], b = psi[j1];
                c32 t0 = cmul(U00, a), t1 = cmul(U01, b);
                c32 t2 = cmul(U10, a), t3 = cmul(U11, b);
                psi[j].x  = t0.x + t1.x; psi[j].y  = t0.y + t1.y;
                psi[j1].x = t2.x + t3.x; psi[j1].y = t2.y + t3.y;
            }
        }
    }

    float z0 = 0.f, z1 = 0.f, z2 = 0.f, z3 = 0.f;
    #pragma unroll
    for (int j = 0; j < 16; j++) {
        float p = fmaf(psi[j].x, psi[j].x, psi[j].y * psi[j].y);
        z0 += (j & 8) ? -p : p;
        z1 += (j & 4) ? -p : p;
        z2 += (j & 2) ? -p : p;
        z3 += (j & 1) ? -p : p;
    }
    return make_float4(z0, z1, z2, z3);
}

__global__ __launch_bounds__(THREADS, 6)
void qp_fused(const float* __restrict__ x,
              const float* __restrict__ pre_w,
              const float* __restrict__ pre_b,
              const float* __restrict__ qw,
              const float* __restrict__ post_w,
              const float* __restrict__ post_b,
              float4* __restrict__ out4)
{
    __shared__ __align__(16) float wsm[4 * 1024];   // pre_w as stored: [q][1024]
    __shared__ float2 rotm[4][4];
    __shared__ float  pbq[4];
    __shared__ float4 zsm[ROWS_BLK];

    const int t = threadIdx.x;
    {
        const float4* src = (const float4*)pre_w;
        float4*       dst = (float4*)wsm;
        #pragma unroll
        for (int i = 0; i < 8; i++) dst[t + THREADS * i] = src[t + THREADS * i];
    }
    if (t < 4) {
        pbq[t] = pre_b[t];
        float phi = qw[t * 3 + 0], th = qw[t * 3 + 1], om = qw[t * 3 + 2];
        float st, ct; sincosf(0.5f * th,         &st, &ct);
        float sp, cp; sincosf(0.5f * (phi + om), &sp, &cp);
        float sm, cm; sincosf(0.5f * (phi - om), &sm, &cm);
        rotm[t][0] = make_float2( ct * cp, -ct * sp);
        rotm[t][1] = make_float2(-st * cm, -st * sm);
        rotm[t][2] = make_float2( st * cm, -st * sm);
        rotm[t][3] = make_float2( ct * cp,  ct * sp);
    }
    __syncthreads();

    const int warp = t >> 5, lane = t & 31;
    const int row0 = blockIdx.x * ROWS_BLK;

    // ---------------- Phase A: h = x @ pre_w.T, 4 rows per warp -----------
    {
        const int rloc = lane >> 3;                // 0..3
        const int cgrp = lane & 7;                 // 0..7
        const int row  = row0 + warp * 4 + rloc;
        const float4* __restrict__ xr = (const float4*)x + (size_t)row * 256 + cgrp;
        const float4* __restrict__ w4a = (const float4*)(wsm);
        const float4* __restrict__ w4b = (const float4*)(wsm + 1024);
        const float4* __restrict__ w4c = (const float4*)(wsm + 2048);
        const float4* __restrict__ w4d = (const float4*)(wsm + 3072);

        float a0 = 0.f, a1 = 0.f, a2 = 0.f, a3 = 0.f;
        #pragma unroll 8
        for (int i = 0; i < 32; i++) {
            const int col = cgrp + 8 * i;
            float4 xv = ldcs256(xr + 8 * i);
            float4 w0 = w4a[col], w1 = w4b[col], w2 = w4c[col], w3 = w4d[col];
            a0 = fmaf(xv.x, w0.x, fmaf(xv.y, w0.y, fmaf(xv.z, w0.z, fmaf(xv.w, w0.w, a0))));
            a1 = fmaf(xv.x, w1.x, fmaf(xv.y, w1.y, fmaf(xv.z, w1.z, fmaf(xv.w, w1.w, a1))));
            a2 = fmaf(xv.x, w2.x, fmaf(xv.y, w2.y, fmaf(xv.z, w2.z, fmaf(xv.w, w2.w, a2))));
            a3 = fmaf(xv.x, w3.x, fmaf(xv.y, w3.y, fmaf(xv.z, w3.z, fmaf(xv.w, w3.w, a3))));
        }
        // reduce across the 8 lanes of each row group
        #pragma unroll
        for (int off = 1; off < 8; off <<= 1) {
            a0 += __shfl_xor_sync(0xffffffffu, a0, off);
            a1 += __shfl_xor_sync(0xffffffffu, a1, off);
            a2 += __shfl_xor_sync(0xffffffffu, a2, off);
            a3 += __shfl_xor_sync(0xffffffffu, a3, off);
        }

        const float f0 = f_tanh(a0 + pbq[0]) * PI_F;
        const float f1 = f_tanh(a1 + pbq[1]) * PI_F;
        const float f2 = f_tanh(a2 + pbq[2]) * PI_F;
        const float f3 = f_tanh(a3 + pbq[3]) * PI_F;

        float4 z = circuit(f0, f1, f2, f3, rotm);
        if (cgrp == 0) zsm[warp * 4 + rloc] = z;
    }
    __syncthreads();

    // ---------------- Phase B: out = z @ post_w.T + post_b ----------------
    // thread t owns float4-columns t and t+128; weights held in registers,
    // reused across all 16 rows.
    {
        const float4* pwv = (const float4*)post_w;
        #pragma unroll
        for (int h = 0; h < 2; h++) {
            const int c = t + 128 * h;
            float4 pw0 = pwv[4 * c + 0];
            float4 pw1 = pwv[4 * c + 1];
            float4 pw2 = pwv[4 * c + 2];
            float4 pw3 = pwv[4 * c + 3];
            float4 bv  = ((const float4*)post_b)[c];

            float4* ocol = out4 + (size_t)row0 * 256 + c;
            #pragma unroll 8
            for (int r = 0; r < ROWS_BLK; r++) {
                float4 zv = zsm[r];
                float4 o;
                o.x = fmaf(zv.x, pw0.x, fmaf(zv.y, pw0.y, fmaf(zv.z, pw0.z, fmaf(zv.w, pw0.w, bv.x))));
                o.y = fmaf(zv.x, pw1.x, fmaf(zv.y, pw1.y, fmaf(zv.z, pw1.z, fmaf(zv.w, pw1.w, bv.y))));
                o.z = fmaf(zv.x, pw2.x, fmaf(zv.y, pw2.y, fmaf(zv.z, pw2.z, fmaf(zv.w, pw2.w, bv.z))));
                o.w = fmaf(zv.x, pw3.x, fmaf(zv.y, pw3.y, fmaf(zv.z, pw3.z, fmaf(zv.w, pw3.w, bv.w))));
                __stcs(ocol + (size_t)r * 256, o);
            }
        }
    }
}

extern "C" void kernel_launch(void* const* d_in, const int* in_sizes, int n_in,
                              void* d_out, int out_size)
{
    const float* x      = (const float*)d_in[0];
    const float* pre_w  = (const float*)d_in[1];
    const float* pre_b  = (const float*)d_in[2];
    const float* qw     = (const float*)d_in[3];
    const float* post_w = (const float*)d_in[4];
    const float* post_b = (const float*)d_in[5];
    (void)in_sizes; (void)n_in; (void)out_size;

    qp_fused<<<BLOCKS, THREADS>>>(x, pre_w, pre_b, qw, post_w, post_b, (float4*)d_out);
}